// round 14
// baseline (speedup 1.0000x reference)
#include <cuda_runtime.h>

// FISTA box-QP denoiser, two passes of 100 iters.
// Fused 5-point D^T D stencil (exact via linear-extrapolated ghosts).
// TWO ROWS PER LANE packed into f32x2, stored NATIVELY as u64 so
// add/mul/fma.rn.f32x2 run with no pack/unpack movs. y in lane-private
// SMEM. 64-thread blocks for fine-grained occupancy (no reg cap).
// (Resubmission of R12 — prior bench was an infra failure.)

#define NCOL 512
#define REG  16
#define NITER 100
#define WPB  2    // warps per block

typedef unsigned long long u64;

// ---- u64-native packed f32x2 ops (sm_103a) ----
__device__ __forceinline__ u64 fadd2(u64 a, u64 b) {
    u64 r; asm("add.rn.f32x2 %0,%1,%2;" : "=l"(r) : "l"(a), "l"(b)); return r;
}
__device__ __forceinline__ u64 fmul2(u64 a, u64 b) {
    u64 r; asm("mul.rn.f32x2 %0,%1,%2;" : "=l"(r) : "l"(a), "l"(b)); return r;
}
__device__ __forceinline__ u64 ffma2(u64 a, u64 b, u64 c) {
    u64 r; asm("fma.rn.f32x2 %0,%1,%2,%3;" : "=l"(r) : "l"(a), "l"(b), "l"(c)); return r;
}
__device__ __forceinline__ u64 pack2(float lo, float hi) {
    u64 r; asm("mov.b64 %0,{%1,%2};" : "=l"(r) : "f"(lo), "f"(hi)); return r;
}
__device__ __forceinline__ u64 bcast2(float s) {
    u64 r; asm("mov.b64 %0,{%1,%1};" : "=l"(r) : "f"(s)); return r;
}
__device__ __forceinline__ void unpack2(u64 v, float& lo, float& hi) {
    asm("mov.b64 {%0,%1},%2;" : "=f"(lo), "=f"(hi) : "l"(v));
}
__device__ __forceinline__ u64 shup64(u64 v) {
    float lo, hi; unpack2(v, lo, hi);
    lo = __shfl_up_sync(0xffffffffu, lo, 1);
    hi = __shfl_up_sync(0xffffffffu, hi, 1);
    return pack2(lo, hi);
}
__device__ __forceinline__ u64 shdn64(u64 v) {
    float lo, hi; unpack2(v, lo, hi);
    lo = __shfl_down_sync(0xffffffffu, lo, 1);
    hi = __shfl_down_sync(0xffffffffu, hi, 1);
    return pack2(lo, hi);
}

__global__ void __launch_bounds__(64)
denoise_fista2(const float* __restrict__ in, float* __restrict__ out, int nrows)
{
    // y: lane-private slots, float2 (8B lane stride, conflict-free LDS.64). 8KB/block.
    __shared__ float2 ysm[WPB][REG][32];

    const int gwarp = (int)((blockIdx.x * blockDim.x + threadIdx.x) >> 5);
    const int wib   = (int)(threadIdx.x >> 5);
    const int lane  = (int)(threadIdx.x & 31);
    const int r0 = 2 * gwarp;
    if (r0 >= nrows) return;

    const float LAM  = 10.0f;
    const float step = 1.0f / (2.0f * (1.0f + 16.0f * LAM));
    // v = Ac*z + Bc*y + Cc*s1 + Dc*s2,  s1=z[i-2]+z[i+2], s2=z[i-1]+z[i+1]
    const u64 A2 = bcast2(1.0f - 2.0f * step - 12.0f * step * LAM);
    const u64 B2 = bcast2(2.0f * step);
    const u64 C2 = bcast2(-2.0f * step * LAM);
    const u64 D2 = bcast2(8.0f * step * LAM);
    const u64 N1 = bcast2(-1.0f);

    const float* __restrict__ sa = in  + (size_t)r0 * NCOL + lane * REG;
    const float* __restrict__ sb = sa + NCOL;

    u64 x[REG], z[REG];
    // load + pass-0 init: x0 = proj(y) = clip(y,0,y); z0 = x0; y -> smem
#pragma unroll
    for (int q = 0; q < REG / 4; q++) {
        float4 va = *reinterpret_cast<const float4*>(sa + 4 * q);
        float4 vb = *reinterpret_cast<const float4*>(sb + 4 * q);
        float pa[4] = {va.x, va.y, va.z, va.w};
        float pb[4] = {vb.x, vb.y, vb.z, vb.w};
#pragma unroll
        for (int u = 0; u < 4; u++) {
            int j = 4 * q + u;
            ysm[wib][j][lane] = make_float2(pa[u], pb[u]);
            float cx = fminf(fmaxf(pa[u], 0.0f), pa[u]);
            float cy = fminf(fmaxf(pb[u], 0.0f), pb[u]);
            u64 p = pack2(cx, cy);
            x[j] = p; z[j] = p;
        }
    }

#pragma unroll 1
    for (int pass = 0; pass < 2; pass++) {
        float t = 1.0f;

#pragma unroll 1
        for (int k = 0; k < NITER; k++) {
            // halos (from OLD z): z[gi-1], z[gi-2], z[gi+16], z[gi+17]
            u64 zu1 = shup64(z[REG - 1]);
            u64 zu2 = shup64(z[REG - 2]);
            u64 zd1 = shdn64(z[0]);
            u64 zd2 = shdn64(z[1]);

            // ghost extrapolation at the global ends:
            //   left:  z[-1]=2z0-z1, z[-2]=2z[-1]-z0
            //   right: z[n]=2z[n-1]-z[n-2], z[n+1]=2z[n]-z[n-1]
            {
                u64 e1 = ffma2(z[1], N1, fadd2(z[0], z[0]));
                u64 e2 = ffma2(z[0], N1, fadd2(e1, e1));
                if (lane == 0) { zu1 = e1; zu2 = e2; }
                u64 f1 = ffma2(z[REG - 2], N1, fadd2(z[REG - 1], z[REG - 1]));
                u64 f2 = ffma2(z[REG - 1], N1, fadd2(f1, f1));
                if (lane == 31) { zd1 = f1; zd2 = f2; }
            }

            // momentum scalar (uniform across lanes & rows)
            float tn = 0.5f * (1.0f + sqrtf(1.0f + 4.0f * t * t));
            float c  = __fdividef(t - 1.0f, tn);
            t = tn;
            const u64 c2 = bcast2(c);

            // rolling OLD backward neighbors (in-place stencil hazard fix)
            u64 zm2 = zu2;
            u64 zm1 = zu1;

#pragma unroll
            for (int j = 0; j < REG; j++) {
                u64 np1 = (j <= REG - 2) ? z[j + 1] : zd1;
                u64 np2 = (j <= REG - 3) ? z[j + 2] : ((j == REG - 2) ? zd1 : zd2);

                float2 yj2 = ysm[wib][j][lane];            // LDS.64, lane-private
                u64 yj = pack2(yj2.x, yj2.y);

                u64 zc = z[j];                             // old center
                u64 s1 = fadd2(zm2, np2);
                u64 s2 = fadd2(zm1, np1);
                u64 w  = ffma2(s2, D2, fmul2(s1, C2));
                u64 v  = ffma2(zc, A2, ffma2(yj, B2, w));

                float vx, vy; unpack2(v, vx, vy);
                float xnx = fminf(fmaxf(vx, 0.0f), yj2.x);
                float xny = fminf(fmaxf(vy, 0.0f), yj2.y);
                u64 xn = pack2(xnx, xny);

                u64 dz = ffma2(x[j], N1, xn);              // xn - x
                zm2 = zm1;                                 // roll OLD values
                zm1 = zc;
                z[j] = ffma2(dz, c2, xn);                  // xn + c*(xn-x)
                x[j] = xn;
            }
        }

        if (pass == 0) {
            // y(pass2) = x; x>=0 so proj(y)=y: x0=x, z0=x. Lane-private, no sync.
#pragma unroll
            for (int j = 0; j < REG; j++) {
                float lo, hi; unpack2(x[j], lo, hi);
                ysm[wib][j][lane] = make_float2(lo, hi);
                z[j] = x[j];
            }
        }
    }

    float* __restrict__ da = out + (size_t)r0 * NCOL + lane * REG;
    float* __restrict__ db = da + NCOL;
#pragma unroll
    for (int q = 0; q < REG / 4; q++) {
        float xl[4], xh[4];
#pragma unroll
        for (int u = 0; u < 4; u++) unpack2(x[4 * q + u], xl[u], xh[u]);
        *reinterpret_cast<float4*>(da + 4 * q) = make_float4(xl[0], xl[1], xl[2], xl[3]);
        *reinterpret_cast<float4*>(db + 4 * q) = make_float4(xh[0], xh[1], xh[2], xh[3]);
    }
}

extern "C" void kernel_launch(void* const* d_in, const int* in_sizes, int n_in,
                              void* d_out, int out_size)
{
    const float* in = (const float*)d_in[0];
    float* out = (float*)d_out;
    const int nrows = in_sizes[0] / NCOL;             // 16384 rows
    const int nwarps = nrows / 2;                     // 2 rows per warp
    const int threads = WPB * 32;                     // 64
    const int blocks = (nwarps + WPB - 1) / WPB;      // 4096
    denoise_fista2<<<blocks, threads>>>(in, out, nrows);
}